// round 11
// baseline (speedup 1.0000x reference)
#include <cuda_runtime.h>
#include <math.h>

#define Bn    128
#define Tn    128
#define In    512
#define Hn    512
#define Dn    1024
#define Nn    513
#define NP    576
#define DEPTH 4
#define EPSV  1e-5f
#define NCTA  296          // 2 CTAs per SM
#define GCTA  148          // CTAs per group
#define GB    64           // batches per group
#define NTHR  256
#define KS    16           // split-K factor in scan
#define SCTA  144          // scan CTAs per group (KS * 9 strips)

typedef unsigned long long u64t;

// ----------------------------- device state --------------------------------
__device__ float g_Wp[Dn * NP];
__device__ float g_Up[Dn * NP];
__device__ float g_X[Tn * Bn * Dn];        // xs / h_seq in place, row = t*Bn+b
__device__ float g_XWraw[Tn * Bn * NP];
__device__ float g_spre[Tn * Bn * NP];
__device__ float g_Gpart[2 * KS * GB * NP];  // [group*16+ks][64 rows][NP]
__device__ float g_h[Bn * Dn];
__device__ float g_fk[Bn];
__device__ float g_hv[Bn];
__device__ float g_fkseq[Tn * Bn];
__device__ float g_hvseq[Tn * Bn];
__device__ unsigned g_barCnt[4];           // 0,1: groups; 2: global
__device__ unsigned g_barEp[4];
__device__ unsigned g_bkCnt[2 * 12];       // scan barrier buckets
__device__ unsigned g_rtCnt[2];
__device__ unsigned g_rtEp[2];

// --------------------------- f32x2 packed math ------------------------------
__device__ __forceinline__ void ffma2(u64t& d, u64t a, u64t b) {
    asm("fma.rn.f32x2 %0, %1, %2, %0;" : "+l"(d) : "l"(a), "l"(b));
}
__device__ __forceinline__ u64t packdup(float x) {
    u64t r; asm("mov.b64 %0, {%1, %1};" : "=l"(r) : "f"(x)); return r;
}
__device__ __forceinline__ float2 unpack2(u64t v) {
    float2 f; asm("mov.b64 {%0, %1}, %2;" : "=f"(f.x), "=f"(f.y) : "l"(v)); return f;
}

// ------------------------------ barriers ------------------------------------
__device__ __forceinline__ unsigned ld_acq(unsigned* p) {
    unsigned v;
    asm volatile("ld.acquire.gpu.u32 %0, [%1];" : "=r"(v) : "l"(p) : "memory");
    return v;
}
__device__ __forceinline__ void barrier_sync(int idx, int n, unsigned& ep) {
    __syncthreads();
    if (threadIdx.x == 0) {
        ep += 1;
        __threadfence();
        unsigned prev = atomicAdd(&g_barCnt[idx], 1u);
        if (prev == (unsigned)(n - 1)) {
            atomicExch(&g_barCnt[idx], 0u);
            __threadfence();
            atomicExch(&g_barEp[idx], ep);
        } else {
            while (ld_acq(&g_barEp[idx]) < ep) { }
        }
        __threadfence();
    }
    __syncthreads();
}
// hierarchical 12x12 barrier for the 144 scan CTAs of group g
__device__ __forceinline__ void scan_barrier(int g, int bkt, unsigned& ep) {
    __syncthreads();
    if (threadIdx.x == 0) {
        ep += 1;
        __threadfence();
        unsigned p = atomicAdd(&g_bkCnt[g * 12 + bkt], 1u);
        if (p == 11u) {
            atomicExch(&g_bkCnt[g * 12 + bkt], 0u);
            __threadfence();
            unsigned q = atomicAdd(&g_rtCnt[g], 1u);
            if (q == 11u) {
                atomicExch(&g_rtCnt[g], 0u);
                __threadfence();
                atomicExch(&g_rtEp[g], ep);
            }
        }
        while (ld_acq(&g_rtEp[g]) < ep) { }
        __threadfence();
    }
    __syncthreads();
}

// --------------------- 64x64 tile GEMM (xW phase) ---------------------------
__device__ __forceinline__ void tile_gemm64(
    const float* __restrict__ A, int lda,
    const float* __restrict__ Bm,
    float* __restrict__ C, int K, float* sh)
{
    float* hT = sh;            // [16][68]
    float* Us = sh + 16 * 68;  // [16][64]
    int tid  = threadIdx.x;
    int arow = tid >> 2, akq = (tid & 3) << 2;
    int brow = tid >> 4, bc  = (tid & 15) << 2;
    int ty   = tid >> 4, tx  = tid & 15;

    u64t acc2[4][2];
#pragma unroll
    for (int i = 0; i < 4; i++) { acc2[i][0] = 0ull; acc2[i][1] = 0ull; }

    const float* Aptr = A + arow * lda + akq;
    const float* Bptr = Bm + brow * NP + bc;
    float4 av = *(const float4*)Aptr;
    float4 bv = *(const float4*)Bptr;

    for (int k0 = 0; k0 < K; k0 += 16) {
        __syncthreads();
        hT[(akq + 0) * 68 + arow] = av.x;
        hT[(akq + 1) * 68 + arow] = av.y;
        hT[(akq + 2) * 68 + arow] = av.z;
        hT[(akq + 3) * 68 + arow] = av.w;
        *(float4*)(Us + (brow << 6) + bc) = bv;
        __syncthreads();
        if (k0 + 16 < K) {
            av = *(const float4*)(Aptr + k0 + 16);
            bv = *(const float4*)(Bptr + (size_t)(k0 + 16) * NP);
        }
#pragma unroll
        for (int kk = 0; kk < 16; kk++) {
            float4 a = *(float4*)(hT + kk * 68 + (ty << 2));
            const u64t* bp = (const u64t*)(Us + (kk << 6) + (tx << 2));
            u64t b0 = bp[0];
            u64t b1 = bp[1];
            u64t ad;
            ad = packdup(a.x); ffma2(acc2[0][0], ad, b0); ffma2(acc2[0][1], ad, b1);
            ad = packdup(a.y); ffma2(acc2[1][0], ad, b0); ffma2(acc2[1][1], ad, b1);
            ad = packdup(a.z); ffma2(acc2[2][0], ad, b0); ffma2(acc2[2][1], ad, b1);
            ad = packdup(a.w); ffma2(acc2[3][0], ad, b0); ffma2(acc2[3][1], ad, b1);
        }
    }
#pragma unroll
    for (int i = 0; i < 4; i++) {
        float2 lo = unpack2(acc2[i][0]);
        float2 hi = unpack2(acc2[i][1]);
        *(float4*)(C + (size_t)((ty << 2) + i) * NP + (tx << 2)) =
            make_float4(lo.x, lo.y, hi.x, hi.y);
    }
}

// ------------------------------ main kernel ---------------------------------
__global__ void __launch_bounds__(NTHR, 2) hrnn_kernel(
    const float* __restrict__ x, const int* __restrict__ mask,
    const float* __restrict__ W, const float* __restrict__ U,
    const float* __restrict__ bias, const float* __restrict__ gam,
    const float* __restrict__ bet, float* __restrict__ out)
{
    __shared__ __align__(16) float sh_U[64 * 64];     // persistent U slice
    __shared__ __align__(16) float sh_hT[64 * 68];    // h stage / xW gemm buf
    __shared__ float sh_s[Nn];
    __shared__ float sh_red[16];
    __shared__ float sh_sc[8];

    int cta = blockIdx.x, tid = threadIdx.x;
    int gtid = cta * NTHR + tid;
    const int nthr = NCTA * NTHR;

    // ------------------------------- prep -----------------------------------
    for (int i = gtid; i < Tn * Bn * Dn; i += nthr) {
        int d = i & (Dn - 1);
        int row = i >> 10;
        int t = row >> 7, b = row & 127;
        g_X[i] = (d < In) ? x[(b * Tn + t) * In + d] : 0.f;
    }
    for (int i = gtid; i < Dn * NP; i += nthr) {
        int col = i % NP, r = i / NP;
        float wv = 0.f, uv = 0.f;
        if (col < Nn) { wv = W[r * Nn + col]; uv = U[r * Nn + col]; }
        g_Wp[i] = wv;
        g_Up[i] = uv;
    }
    for (int i = gtid; i < Tn * Bn; i += nthr) { g_fkseq[i] = 0.f; g_hvseq[i] = 1.f; }

    int g = cta & 1;         // group interleave: each SM hosts one CTA per group
    int c = cta >> 1;
    unsigned epG = 0, epL = 0, epS = 0;
    if (tid == 0) {
        epG = ld_acq(&g_barEp[2]);
        epL = ld_acq(&g_barEp[g]);
        epS = ld_acq(&g_rtEp[g]);
    }
    barrier_sync(2, NCTA, epG);

    const float* gam0 = gam;
    const float* gam1 = gam + Nn;
    const float* bet0 = bet;
    const float* bet1 = bet + Nn;
    const int b0g = g * GB;

    // scan-role constants
    int ks = c / 9, j = c - ks * 9;          // valid for c < SCTA
    int bkt = c % 12;
    int ty = tid >> 4, tx = tid & 15;

    // load persistent U slice once (64 K-rows x 64 cols)
    if (c < SCTA) {
        for (int i = tid; i < 1024; i += NTHR) {
            int idx = i << 2;
            int kk = idx >> 6, c4 = idx & 63;
            *(float4*)&sh_U[idx] =
                *(const float4*)&g_Up[(size_t)(ks * 64 + kk) * NP + j * 64 + c4];
        }
    }

    for (int lev = 0; lev < DEPTH; lev++) {
        // ---------------- xW GEMM: 128 t-tiles x 9 col strips ----------------
        for (int tau = c; tau < Tn * 9; tau += GCTA) {
            int t = tau / 9, jj = tau - t * 9;
            tile_gemm64(&g_X[(size_t)(t * Bn + b0g) * Dn], Dn,
                        &g_Wp[jj * 64],
                        &g_XWraw[(size_t)(t * Bn + b0g) * NP + jj * 64],
                        Dn, sh_hT);
        }
        barrier_sync(g, GCTA, epL);

        // ---------------- LN of xW rows -> spre; init carries ----------------
        for (int lr = c; lr < Tn * GB; lr += GCTA) {
            int t = lr >> 6, bl = lr & 63;
            const float* row = &g_XWraw[(size_t)(t * Bn + b0g + bl) * NP];
            float v0 = row[tid];
            float v1 = row[tid + 256];
            float v2 = (tid == 0) ? row[512] : 0.f;
            float s = v0 + v1 + v2;
            float q = v0 * v0 + v1 * v1 + v2 * v2;
#pragma unroll
            for (int o = 16; o > 0; o >>= 1) {
                s += __shfl_down_sync(0xffffffffu, s, o);
                q += __shfl_down_sync(0xffffffffu, q, o);
            }
            if ((tid & 31) == 0) { sh_red[tid >> 5] = s; sh_red[8 + (tid >> 5)] = q; }
            __syncthreads();
            if (tid == 0) {
                float S = 0.f, Q = 0.f;
#pragma unroll
                for (int w = 0; w < 8; w++) { S += sh_red[w]; Q += sh_red[8 + w]; }
                float mean = S * (1.f / (float)Nn);
                float var  = Q * (1.f / (float)Nn) - mean * mean;
                sh_sc[0] = mean;
                sh_sc[1] = 1.f / (sqrtf(var + EPSV) + EPSV);
            }
            __syncthreads();
            float mean = sh_sc[0], inv = sh_sc[1];
            float* o = &g_spre[(size_t)(t * Bn + b0g + bl) * NP];
            o[tid]       = gam0[tid] * ((v0 - mean) * inv) + bet0[tid] + bias[tid];
            o[tid + 256] = gam0[tid + 256] * ((v1 - mean) * inv) + bet0[tid + 256] + bias[tid + 256];
            if (tid == 0)
                o[512] = gam0[512] * ((v2 - mean) * inv) + bet0[512] + bias[512];
            __syncthreads();
        }
        for (int i = c * NTHR + tid; i < GB * Dn; i += GCTA * NTHR)
            g_h[(size_t)b0g * Dn + i] = 0.f;
        for (int i = c * NTHR + tid; i < GB; i += GCTA * NTHR) {
            g_fk[b0g + i] = 0.f;
            g_hv[b0g + i] = 0.f;
        }
        barrier_sync(g, GCTA, epL);

        // ------------------------------ scan ---------------------------------
        if (c < SCTA) {
            for (int t = 0; t < Tn; t++) {
                // ---- phase A: stage h block (transposed), FFMA vs resident U
                {
                    int row = tid >> 2, ko = (tid & 3) << 4;
                    const float* hr = &g_h[(size_t)(b0g + row) * Dn + ks * 64 + ko];
                    float4 a0 = *(const float4*)(hr);
                    float4 a1 = *(const float4*)(hr + 4);
                    float4 a2 = *(const float4*)(hr + 8);
                    float4 a3 = *(const float4*)(hr + 12);
                    sh_hT[(ko + 0) * 68 + row] = a0.x;
                    sh_hT[(ko + 1) * 68 + row] = a0.y;
                    sh_hT[(ko + 2) * 68 + row] = a0.z;
                    sh_hT[(ko + 3) * 68 + row] = a0.w;
                    sh_hT[(ko + 4) * 68 + row] = a1.x;
                    sh_hT[(ko + 5) * 68 + row] = a1.y;
                    sh_hT[(ko + 6) * 68 + row] = a1.z;
                    sh_hT[(ko + 7) * 68 + row] = a1.w;
                    sh_hT[(ko + 8) * 68 + row] = a2.x;
                    sh_hT[(ko + 9) * 68 + row] = a2.y;
                    sh_hT[(ko + 10) * 68 + row] = a2.z;
                    sh_hT[(ko + 11) * 68 + row] = a2.w;
                    sh_hT[(ko + 12) * 68 + row] = a3.x;
                    sh_hT[(ko + 13) * 68 + row] = a3.y;
                    sh_hT[(ko + 14) * 68 + row] = a3.z;
                    sh_hT[(ko + 15) * 68 + row] = a3.w;
                    __syncthreads();

                    u64t acc2[4][2];
#pragma unroll
                    for (int i = 0; i < 4; i++) { acc2[i][0] = 0ull; acc2[i][1] = 0ull; }
#pragma unroll 16
                    for (int kk = 0; kk < 64; kk++) {
                        float4 a = *(float4*)&sh_hT[kk * 68 + (ty << 2)];
                        const u64t* up = (const u64t*)&sh_U[(kk << 6) + (tx << 2)];
                        u64t b0 = up[0];
                        u64t b1 = up[1];
                        u64t ad;
                        ad = packdup(a.x); ffma2(acc2[0][0], ad, b0); ffma2(acc2[0][1], ad, b1);
                        ad = packdup(a.y); ffma2(acc2[1][0], ad, b0); ffma2(acc2[1][1], ad, b1);
                        ad = packdup(a.z); ffma2(acc2[2][0], ad, b0); ffma2(acc2[2][1], ad, b1);
                        ad = packdup(a.w); ffma2(acc2[3][0], ad, b0); ffma2(acc2[3][1], ad, b1);
                    }
#pragma unroll
                    for (int i = 0; i < 4; i++) {
                        float2 lo = unpack2(acc2[i][0]);
                        float2 hi = unpack2(acc2[i][1]);
                        *(float4*)&g_Gpart[(size_t)((g * KS + ks) * GB + (ty << 2) + i) * NP
                                           + j * 64 + (tx << 2)] =
                            make_float4(lo.x, lo.y, hi.x, hi.y);
                    }
                    __syncthreads();   // sh_hT free before next use
                }
                scan_barrier(g, bkt, epS);

                // ---- phase B: one CTA per batch
                if (c < GB) {
                    int b = b0g + c;
                    // hoist serial-gate operands (latency hides under reduce)
                    float fk_tm1 = 0.f, hv_tm1 = 0.f, fkp_tm1 = 0.f, fkp = 0.f, hvp = 0.f;
                    int mval = 0, mprev = 0;
                    if (tid == 0) {
                        fk_tm1  = g_fk[b];
                        hv_tm1  = g_hv[b];
                        fkp_tm1 = g_fkseq[t * Bn + b];
                        fkp     = (t + 1 < Tn) ? g_fkseq[(t + 1) * Bn + b] : 0.f;
                        hvp     = g_hvseq[t * Bn + b];
                        mval    = mask[b * Tn + t];
                        mprev   = (t > 0) ? mask[b * Tn + t - 1] : 0;
                    }

                    float v0 = 0.f, v1 = 0.f, v2 = 0.f;
#pragma unroll
                    for (int kq = 0; kq < KS; kq++) {
                        const float* gp = &g_Gpart[(size_t)((g * KS + kq) * GB + c) * NP];
                        v0 += gp[tid];
                        v1 += gp[tid + 256];
                        if (tid == 0) v2 += gp[512];
                    }
                    float s = v0 + v1 + v2;
                    float q = v0 * v0 + v1 * v1 + v2 * v2;
#pragma unroll
                    for (int o = 16; o > 0; o >>= 1) {
                        s += __shfl_down_sync(0xffffffffu, s, o);
                        q += __shfl_down_sync(0xffffffffu, q, o);
                    }
                    if ((tid & 31) == 0) { sh_red[tid >> 5] = s; sh_red[8 + (tid >> 5)] = q; }
                    __syncthreads();
                    if (tid == 0) {
                        float S = 0.f, Q = 0.f;
#pragma unroll
                        for (int w = 0; w < 8; w++) { S += sh_red[w]; Q += sh_red[8 + w]; }
                        float mean = S * (1.f / (float)Nn);
                        float var  = Q * (1.f / (float)Nn) - mean * mean;
                        sh_sc[0] = mean;
                        sh_sc[1] = 1.f / (sqrtf(var + EPSV) + EPSV);
                    }
                    __syncthreads();
                    float mean = sh_sc[0], inv = sh_sc[1];

                    const float* sp = &g_spre[(size_t)(t * Bn + b) * NP];
                    float sum2_0 = gam1[0] * ((v0 - mean) * inv) + bet1[0]; // tid 0 only
                    float s0 = sp[tid]       + gam1[tid]       * ((v0 - mean) * inv) + bet1[tid];
                    float s1 = sp[tid + 256] + gam1[tid + 256] * ((v1 - mean) * inv) + bet1[tid + 256];
                    sh_s[tid]       = s0;
                    sh_s[tid + 256] = s1;
                    if (tid == 0)
                        sh_s[512] = sp[512] + gam1[512] * ((v2 - mean) * inv) + bet1[512];

                    if (tid == 0) {
                        bool mk  = mval > 0;
                        bool mk2 = (t > 0) && (mprev > 0) && !mk;

                        float fk_both = fminf(fmaxf(0.2f * s0 + 0.5f, 0.f), 1.f);
                        float fk_t1   = fminf(fmaxf(0.2f * (sum2_0 + bias[0]) + 0.5f, 0.f), 1.f);
                        float fk = fkp_tm1 + (1.f - fkp_tm1) *
                                   (fk_tm1 * fk_both + (1.f - fk_tm1) * fk_t1);
                        if (mk2) fk = 0.f;

                        float h_only = hv_tm1 * fk * (fkp + (1.f - fkp) * (1.f - hvp));
                        float x_only = hvp * (1.f - fkp) * (1.f - fk + fk * (1.f - hv_tm1));
                        float both   = (1.f - fkp) * fk * hv_tm1 * hvp;
                        float hv = 1.f - (1.f - h_only) * (1.f - x_only) * (1.f - both);

                        float fk_out = mk ? fk : fk_tm1;
                        float hv_out = mk ? hv : hv_tm1;
                        if (mk2) fk_out = 0.f;

                        sh_sc[2] = h_only; sh_sc[3] = x_only;
                        sh_sc[4] = both;   sh_sc[5] = mk ? 1.f : 0.f;

                        g_fk[b] = fk_out;
                        g_hv[b] = hv_out;
                        g_fkseq[t * Bn + b] = fk_out;
                        g_hvseq[t * Bn + b] = hv_out;
                    }
                    __syncthreads();

                    float h_only = sh_sc[2], x_only = sh_sc[3];
                    float both = sh_sc[4], mkf = sh_sc[5];
#pragma unroll
                    for (int e = 0; e < 4; e++) {
                        int d = tid + (e << 8);
                        float x_t   = g_X[(size_t)(t * Bn + b) * Dn + d];
                        float h_tm1 = g_h[(size_t)b * Dn + d];
                        float h_new = (d < In) ? 0.f : tanhf(sh_s[d - (In - 1)]);
                        float h = h_only * h_tm1 + x_only * x_t + both * h_new;
                        h = mkf * h + (1.f - mkf) * h_tm1;
                        g_h[(size_t)b * Dn + d] = h;
                        g_X[(size_t)(t * Bn + b) * Dn + d] = h;
                    }
                }
                scan_barrier(g, bkt, epS);
            }
        }
        barrier_sync(g, GCTA, epL);
    }

    // ------------------------------ output ----------------------------------
    for (int i = c * NTHR + tid; i < GB * Hn; i += GCTA * NTHR) {
        int bl = i >> 9, jj = i & 511;
        out[(size_t)(b0g + bl) * Hn + jj] = g_h[(size_t)(b0g + bl) * Dn + In + jj];
    }
}

// ------------------------------- launcher -----------------------------------
extern "C" void kernel_launch(void* const* d_in, const int* in_sizes, int n_in,
                              void* d_out, int out_size) {
    const float* x      = (const float*)d_in[0];
    const int*   mask   = (const int*)d_in[1];
    const float* W      = (const float*)d_in[2];
    const float* U      = (const float*)d_in[3];
    const float* bias   = (const float*)d_in[4];
    const float* gammas = (const float*)d_in[5];
    const float* betas  = (const float*)d_in[6];
    float* out = (float*)d_out;

    hrnn_kernel<<<NCTA, NTHR>>>(x, mask, W, U, bias, gammas, betas, out);
}

// round 12
// speedup vs baseline: 1.0235x; 1.0235x over previous
#include <cuda_runtime.h>
#include <math.h>

#define Bn    128
#define Tn    128
#define In    512
#define Hn    512
#define Dn    1024
#define Nn    513
#define NP    576
#define DEPTH 4
#define EPSV  1e-5f
#define NCTA  148
#define NTHR  256
#define KS    16
#define SCTA  144      // KS * 9 strips

typedef unsigned long long u64t;

// ----------------------------- device state --------------------------------
__device__ float g_Wp[Dn * NP];
__device__ float g_Up[Dn * NP];
__device__ float g_X[Tn * Bn * Dn];       // xs / h_seq in place, row = t*Bn+b
__device__ float g_XWraw[Tn * Bn * NP];
__device__ float g_spre[Tn * Bn * NP];
__device__ float g_Gpart[KS * Bn * NP];   // [ks][128 rows][NP]
__device__ float g_h[Bn * Dn];
__device__ float g_fk[Bn];
__device__ float g_hv[Bn];
__device__ float g_fkseq[Tn * Bn];
__device__ float g_hvseq[Tn * Bn];
__device__ unsigned g_ctr;                // monotonic barrier counter
__device__ unsigned g_pCnt, g_pEp;        // legacy prep barrier

// --------------------------- f32x2 packed math ------------------------------
__device__ __forceinline__ void ffma2(u64t& d, u64t a, u64t b) {
    asm("fma.rn.f32x2 %0, %1, %2, %0;" : "+l"(d) : "l"(a), "l"(b));
}
__device__ __forceinline__ u64t packdup(float x) {
    u64t r; asm("mov.b64 %0, {%1, %1};" : "=l"(r) : "f"(x)); return r;
}
__device__ __forceinline__ float2 unpack2(u64t v) {
    float2 f; asm("mov.b64 {%0, %1}, %2;" : "=f"(f.x), "=f"(f.y) : "l"(v)); return f;
}

// ------------------------------ barriers ------------------------------------
__device__ __forceinline__ unsigned ld_acq(unsigned* p) {
    unsigned v;
    asm volatile("ld.acquire.gpu.u32 %0, [%1];" : "=r"(v) : "l"(p) : "memory");
    return v;
}
// legacy epoch barrier (prep only)
__device__ __forceinline__ void prep_barrier(unsigned& ep) {
    __syncthreads();
    if (threadIdx.x == 0) {
        ep += 1;
        __threadfence();
        unsigned prev = atomicAdd(&g_pCnt, 1u);
        if (prev == (unsigned)(NCTA - 1)) {
            atomicExch(&g_pCnt, 0u);
            __threadfence();
            atomicExch(&g_pEp, ep);
        } else {
            while (ld_acq(&g_pEp) < ep) { }
        }
        __threadfence();
    }
    __syncthreads();
}
// monotonic-counter barrier: RED arrival + acquire poll. base sampled pre-prep.
__device__ __forceinline__ void fastbar(unsigned base, unsigned& k) {
    __syncthreads();
    if (threadIdx.x == 0) {
        k += (unsigned)NCTA;
        __threadfence();
        asm volatile("red.release.gpu.add.u32 [%0], 1;" :: "l"(&g_ctr) : "memory");
        while ((unsigned)(ld_acq(&g_ctr) - base) < k) { }
        __threadfence();
    }
    __syncthreads();
}

// ------------------- staging helpers (all 256 threads) ----------------------
// A chunk: 128 rows x 64 k, transposed into hT[k][row], stride 132
__device__ __forceinline__ void stage_A(float* hT, const float* A, int lda, int k0) {
    int tid = threadIdx.x;
    int row = tid & 127;
    int kh  = (tid >> 7) << 5;       // 0 or 32
    const float* src = A + (size_t)row * lda + k0 + kh;
#pragma unroll
    for (int q = 0; q < 8; q++) {
        float4 v = *(const float4*)(src + (q << 2));
        int k = kh + (q << 2);
        hT[(k + 0) * 132 + row] = v.x;
        hT[(k + 1) * 132 + row] = v.y;
        hT[(k + 2) * 132 + row] = v.z;
        hT[(k + 3) * 132 + row] = v.w;
    }
}
// B chunk: 64 k x 64 cols from Bg (row stride NP) into Usm[k*64 + c]
__device__ __forceinline__ void stage_B(float* Usm, const float* Bg, int k0, int n0) {
    int tid = threadIdx.x;
    int kr = tid >> 2;
    int cq = (tid & 3) << 4;
    const float* src = Bg + (size_t)(k0 + kr) * NP + n0 + cq;
#pragma unroll
    for (int q = 0; q < 4; q++)
        *(float4*)&Usm[(kr << 6) + cq + (q << 2)] = *(const float4*)(src + (q << 2));
}

// ---------------- 128x64 GEMM chunk (tid<128 only, 8x8 microtile) -----------
__device__ __forceinline__ void gemm_chunk(u64t acc[8][4], const float* hT,
                                           const float* Usm, int ty, int tx) {
#pragma unroll 8
    for (int kk = 0; kk < 64; kk++) {
        const float* ap = hT + kk * 132 + (ty << 3);
        float4 a0 = *(const float4*)ap;
        float4 a1 = *(const float4*)(ap + 4);
        const u64t* up = (const u64t*)(Usm + (kk << 6) + (tx << 3));
        u64t b0 = up[0], b1 = up[1], b2 = up[2], b3 = up[3];
        u64t ad;
        ad = packdup(a0.x); ffma2(acc[0][0], ad, b0); ffma2(acc[0][1], ad, b1);
                            ffma2(acc[0][2], ad, b2); ffma2(acc[0][3], ad, b3);
        ad = packdup(a0.y); ffma2(acc[1][0], ad, b0); ffma2(acc[1][1], ad, b1);
                            ffma2(acc[1][2], ad, b2); ffma2(acc[1][3], ad, b3);
        ad = packdup(a0.z); ffma2(acc[2][0], ad, b0); ffma2(acc[2][1], ad, b1);
                            ffma2(acc[2][2], ad, b2); ffma2(acc[2][3], ad, b3);
        ad = packdup(a0.w); ffma2(acc[3][0], ad, b0); ffma2(acc[3][1], ad, b1);
                            ffma2(acc[3][2], ad, b2); ffma2(acc[3][3], ad, b3);
        ad = packdup(a1.x); ffma2(acc[4][0], ad, b0); ffma2(acc[4][1], ad, b1);
                            ffma2(acc[4][2], ad, b2); ffma2(acc[4][3], ad, b3);
        ad = packdup(a1.y); ffma2(acc[5][0], ad, b0); ffma2(acc[5][1], ad, b1);
                            ffma2(acc[5][2], ad, b2); ffma2(acc[5][3], ad, b3);
        ad = packdup(a1.z); ffma2(acc[6][0], ad, b0); ffma2(acc[6][1], ad, b1);
                            ffma2(acc[6][2], ad, b2); ffma2(acc[6][3], ad, b3);
        ad = packdup(a1.w); ffma2(acc[7][0], ad, b0); ffma2(acc[7][1], ad, b1);
                            ffma2(acc[7][2], ad, b2); ffma2(acc[7][3], ad, b3);
    }
}
__device__ __forceinline__ void write_tile(u64t acc[8][4], float* C, int ldc,
                                           int ty, int tx) {
#pragma unroll
    for (int i = 0; i < 8; i++) {
        float2 p0 = unpack2(acc[i][0]), p1 = unpack2(acc[i][1]);
        float2 p2 = unpack2(acc[i][2]), p3 = unpack2(acc[i][3]);
        float* cp = C + (size_t)((ty << 3) + i) * ldc + (tx << 3);
        *(float4*)cp       = make_float4(p0.x, p0.y, p1.x, p1.y);
        *(float4*)(cp + 4) = make_float4(p2.x, p2.y, p3.x, p3.y);
    }
}

// ------------------------------ main kernel ---------------------------------
__global__ void __launch_bounds__(NTHR, 1) hrnn_kernel(
    const float* __restrict__ x, const int* __restrict__ mask,
    const float* __restrict__ W, const float* __restrict__ U,
    const float* __restrict__ bias, const float* __restrict__ gam,
    const float* __restrict__ bet, float* __restrict__ out)
{
    __shared__ __align__(16) float sh_U[64 * 64];      // B / persistent U slice
    __shared__ __align__(16) float sh_hT[64 * 132];    // staged A^T chunk
    __shared__ float sh_s[Nn];
    __shared__ float sh_red[16];
    __shared__ float sh_sc[8];

    int cta = blockIdx.x, tid = threadIdx.x;
    int gtid = cta * NTHR + tid;
    const int nthr = NCTA * NTHR;

    // ------------------------------- prep -----------------------------------
    for (int i = gtid; i < Tn * Bn * Dn; i += nthr) {
        int d = i & (Dn - 1);
        int row = i >> 10;
        int t = row >> 7, b = row & 127;
        g_X[i] = (d < In) ? x[(b * Tn + t) * In + d] : 0.f;
    }
    for (int i = gtid; i < Dn * NP; i += nthr) {
        int col = i % NP, r = i / NP;
        float wv = 0.f, uv = 0.f;
        if (col < Nn) { wv = W[r * Nn + col]; uv = U[r * Nn + col]; }
        g_Wp[i] = wv;
        g_Up[i] = uv;
    }
    for (int i = gtid; i < Tn * Bn; i += nthr) { g_fkseq[i] = 0.f; g_hvseq[i] = 1.f; }

    unsigned base = 0, kbar = 0, epP = 0;
    if (tid == 0) {
        base = ld_acq(&g_ctr);       // must precede any red-arrival this launch
        epP  = ld_acq(&g_pEp);
    }
    prep_barrier(epP);

    const float* gam0 = gam;
    const float* gam1 = gam + Nn;
    const float* bet0 = bet;
    const float* bet1 = bet + Nn;

    int ks = cta / 9, j = cta - ks * 9;   // scan role (cta < SCTA)
    int ty = tid >> 3, tx = tid & 7;      // gemm role (tid < 128)
    u64t acc[8][4];

    for (int lev = 0; lev < DEPTH; lev++) {
        // -------- xW GEMM: 1152 tiles of 128x64, K=1024 ----------------------
        for (int tau = cta; tau < Tn * 9; tau += NCTA) {
            int t = tau / 9, jj = tau - t * 9;
            if (tid < 128) {
#pragma unroll
                for (int i = 0; i < 8; i++) {
                    acc[i][0] = 0ull; acc[i][1] = 0ull;
                    acc[i][2] = 0ull; acc[i][3] = 0ull;
                }
            }
            const float* Abase = &g_X[(size_t)(t * Bn) * Dn];
            for (int ch = 0; ch < 16; ch++) {
                __syncthreads();
                stage_A(sh_hT, Abase, Dn, ch * 64);
                stage_B(sh_U, g_Wp, ch * 64, jj * 64);
                __syncthreads();
                if (tid < 128) gemm_chunk(acc, sh_hT, sh_U, ty, tx);
            }
            if (tid < 128)
                write_tile(acc, &g_XWraw[(size_t)(t * Bn) * NP + jj * 64], NP, ty, tx);
        }
        fastbar(base, kbar);

        // -------- LN of xW rows -> spre; init carries ------------------------
        for (int r = cta; r < Tn * Bn; r += NCTA) {
            const float* row = &g_XWraw[(size_t)r * NP];
            float v0 = row[tid];
            float v1 = row[tid + 256];
            float v2 = (tid == 0) ? row[512] : 0.f;
            float s = v0 + v1 + v2;
            float q = v0 * v0 + v1 * v1 + v2 * v2;
#pragma unroll
            for (int o = 16; o > 0; o >>= 1) {
                s += __shfl_down_sync(0xffffffffu, s, o);
                q += __shfl_down_sync(0xffffffffu, q, o);
            }
            if ((tid & 31) == 0) { sh_red[tid >> 5] = s; sh_red[8 + (tid >> 5)] = q; }
            __syncthreads();
            if (tid == 0) {
                float S = 0.f, Q = 0.f;
#pragma unroll
                for (int w = 0; w < 8; w++) { S += sh_red[w]; Q += sh_red[8 + w]; }
                float mean = S * (1.f / (float)Nn);
                float var  = Q * (1.f / (float)Nn) - mean * mean;
                sh_sc[0] = mean;
                sh_sc[1] = 1.f / (sqrtf(var + EPSV) + EPSV);
            }
            __syncthreads();
            float mean = sh_sc[0], inv = sh_sc[1];
            float* o = &g_spre[(size_t)r * NP];
            o[tid]       = gam0[tid] * ((v0 - mean) * inv) + bet0[tid] + bias[tid];
            o[tid + 256] = gam0[tid + 256] * ((v1 - mean) * inv) + bet0[tid + 256] + bias[tid + 256];
            if (tid == 0)
                o[512] = gam0[512] * ((v2 - mean) * inv) + bet0[512] + bias[512];
            __syncthreads();
        }
        for (int i = gtid; i < Bn * Dn; i += nthr) g_h[i] = 0.f;
        for (int i = gtid; i < Bn; i += nthr) { g_fk[i] = 0.f; g_hv[i] = 0.f; }
        fastbar(base, kbar);

        // -------- reload persistent U slice for the scan ---------------------
        if (cta < SCTA) stage_B(sh_U, g_Up, ks * 64, j * 64);

        // ------------------------------ scan ---------------------------------
        for (int t = 0; t < Tn; t++) {
            // phase A: h@U partial (128 x 64, K-chunk 64) vs resident U
            __syncthreads();
            if (cta < SCTA) stage_A(sh_hT, g_h, Dn, ks * 64);
            __syncthreads();
            if (cta < SCTA && tid < 128) {
#pragma unroll
                for (int i = 0; i < 8; i++) {
                    acc[i][0] = 0ull; acc[i][1] = 0ull;
                    acc[i][2] = 0ull; acc[i][3] = 0ull;
                }
                gemm_chunk(acc, sh_hT, sh_U, ty, tx);
                write_tile(acc, &g_Gpart[(size_t)(ks * Bn) * NP + j * 64], NP, ty, tx);
            }
            fastbar(base, kbar);

            // phase B: one CTA per batch
            if (cta < Bn) {
                int b = cta;
                float fk_tm1 = 0.f, hv_tm1 = 0.f, fkp_tm1 = 0.f, fkp = 0.f, hvp = 0.f;
                int mval = 0, mprev = 0;
                if (tid == 0) {
                    fk_tm1  = g_fk[b];
                    hv_tm1  = g_hv[b];
                    fkp_tm1 = g_fkseq[t * Bn + b];
                    fkp     = (t + 1 < Tn) ? g_fkseq[(t + 1) * Bn + b] : 0.f;
                    hvp     = g_hvseq[t * Bn + b];
                    mval    = mask[b * Tn + t];
                    mprev   = (t > 0) ? mask[b * Tn + t - 1] : 0;
                }
                float v0 = 0.f, v1 = 0.f, v2 = 0.f;
#pragma unroll
                for (int kq = 0; kq < KS; kq++) {
                    const float* gp = &g_Gpart[(size_t)(kq * Bn + b) * NP];
                    v0 += gp[tid];
                    v1 += gp[tid + 256];
                    if (tid == 0) v2 += gp[512];
                }
                float s = v0 + v1 + v2;
                float q = v0 * v0 + v1 * v1 + v2 * v2;
#pragma unroll
                for (int o = 16; o > 0; o >>= 1) {
                    s += __shfl_down_sync(0xffffffffu, s, o);
                    q += __shfl_down_sync(0xffffffffu, q, o);
                }
                if ((tid & 31) == 0) { sh_red[tid >> 5] = s; sh_red[8 + (tid >> 5)] = q; }
                __syncthreads();
                if (tid == 0) {
                    float S = 0.f, Q = 0.f;
#pragma unroll
                    for (int w = 0; w < 8; w++) { S += sh_red[w]; Q += sh_red[8 + w]; }
                    float mean = S * (1.f / (float)Nn);
                    float var  = Q * (1.f / (float)Nn) - mean * mean;
                    sh_sc[0] = mean;
                    sh_sc[1] = 1.f / (sqrtf(var + EPSV) + EPSV);
                }
                __syncthreads();
                float mean = sh_sc[0], inv = sh_sc[1];

                const float* sp = &g_spre[(size_t)(t * Bn + b) * NP];
                float sum2_0 = gam1[0] * ((v0 - mean) * inv) + bet1[0]; // tid 0 only
                float s0 = sp[tid]       + gam1[tid]       * ((v0 - mean) * inv) + bet1[tid];
                float s1 = sp[tid + 256] + gam1[tid + 256] * ((v1 - mean) * inv) + bet1[tid + 256];
                sh_s[tid]       = s0;
                sh_s[tid + 256] = s1;
                if (tid == 0)
                    sh_s[512] = sp[512] + gam1[512] * ((v2 - mean) * inv) + bet1[512];

                if (tid == 0) {
                    bool mk  = mval > 0;
                    bool mk2 = (t > 0) && (mprev > 0) && !mk;

                    float fk_both = fminf(fmaxf(0.2f * s0 + 0.5f, 0.f), 1.f);
                    float fk_t1   = fminf(fmaxf(0.2f * (sum2_0 + bias[0]) + 0.5f, 0.f), 1.f);
                    float fk = fkp_tm1 + (1.f - fkp_tm1) *
                               (fk_tm1 * fk_both + (1.f - fk_tm1) * fk_t1);
                    if (mk2) fk = 0.f;

                    float h_only = hv_tm1 * fk * (fkp + (1.f - fkp) * (1.f - hvp));
                    float x_only = hvp * (1.f - fkp) * (1.f - fk + fk * (1.f - hv_tm1));
                    float both   = (1.f - fkp) * fk * hv_tm1 * hvp;
                    float hv = 1.f - (1.f - h_only) * (1.f - x_only) * (1.f - both);

                    float fk_out = mk ? fk : fk_tm1;
                    float hv_out = mk ? hv : hv_tm1;
                    if (mk2) fk_out = 0.f;

                    sh_sc[2] = h_only; sh_sc[3] = x_only;
                    sh_sc[4] = both;   sh_sc[5] = mk ? 1.f : 0.f;

                    g_fk[b] = fk_out;
                    g_hv[b] = hv_out;
                    g_fkseq[t * Bn + b] = fk_out;
                    g_hvseq[t * Bn + b] = hv_out;
                }
                __syncthreads();

                float h_only = sh_sc[2], x_only = sh_sc[3];
                float both = sh_sc[4], mkf = sh_sc[5];
#pragma unroll
                for (int e = 0; e < 4; e++) {
                    int d = tid + (e << 8);
                    float x_t   = g_X[(size_t)(t * Bn + b) * Dn + d];
                    float h_tm1 = g_h[(size_t)b * Dn + d];
                    float h_new = (d < In) ? 0.f : tanhf(sh_s[d - (In - 1)]);
                    float h = h_only * h_tm1 + x_only * x_t + both * h_new;
                    h = mkf * h + (1.f - mkf) * h_tm1;
                    g_h[(size_t)b * Dn + d] = h;
                    g_X[(size_t)(t * Bn + b) * Dn + d] = h;
                }
            }
            fastbar(base, kbar);
        }
    }

    // ------------------------------ output ----------------------------------
    for (int i = gtid; i < Bn * Hn; i += nthr) {
        int b = i >> 9, jj = i & 511;
        out[i] = g_h[(size_t)b * Dn + In + jj];
    }
}

// ------------------------------- launcher -----------------------------------
extern "C" void kernel_launch(void* const* d_in, const int* in_sizes, int n_in,
                              void* d_out, int out_size) {
    const float* x      = (const float*)d_in[0];
    const int*   mask   = (const int*)d_in[1];
    const float* W      = (const float*)d_in[2];
    const float* U      = (const float*)d_in[3];
    const float* bias   = (const float*)d_in[4];
    const float* gammas = (const float*)d_in[5];
    const float* betas  = (const float*)d_in[6];
    float* out = (float*)d_out;

    hrnn_kernel<<<NCTA, NTHR>>>(x, mask, W, U, bias, gammas, betas, out);
}